// round 8
// baseline (speedup 1.0000x reference)
#include <cuda_runtime.h>
#include <cstdint>

#define BB   16
#define CC   256
#define HH   64
#define WW   192
#define DD   25
#define HWs  (HH*WW)
#define CHW  (512*HH*WW)
#define X2OFF ((size_t)CC*HWs)

__device__ float g_corr[(size_t)BB*DD*HH*WW];

// split f0,f1 into packed bf16x2 hi and lo parts (f = hi + lo exactly in fp32 before lo-rounding)
__device__ __forceinline__ void split2(float f0, float f1, uint32_t& hi, uint32_t& lo) {
    asm("cvt.rn.bf16x2.f32 %0, %1, %2;" : "=r"(hi) : "f"(f1), "f"(f0));  // lo16=f0, hi16=f1
    float h0 = __uint_as_float(hi << 16);
    float h1 = __uint_as_float(hi & 0xffff0000u);
    float l0 = f0 - h0;
    float l1 = f1 - h1;
    asm("cvt.rn.bf16x2.f32 %0, %1, %2;" : "=r"(lo) : "f"(l1), "f"(l0));
}

__device__ __forceinline__ void mma_bf16(float* d, const uint32_t* a, const uint32_t* b) {
    asm volatile("mma.sync.aligned.m16n8k16.row.col.f32.bf16.bf16.f32 "
        "{%0,%1,%2,%3}, {%4,%5,%6,%7}, {%8,%9}, {%0,%1,%2,%3};"
        : "+f"(d[0]), "+f"(d[1]), "+f"(d[2]), "+f"(d[3])
        : "r"(a[0]), "r"(a[1]), "r"(a[2]), "r"(a[3]), "r"(b[0]), "r"(b[1]));
}

// D[w][n] = sum_c x1[c][w] * x2pad[c][n],  n = w + 24 - d.
// One CTA per (b,h); warp m owns w-tile [16m,16m+16), n8-tiles 2m..2m+4 (band).
__global__ __launch_bounds__(384)
void corr_mma(const float* __restrict__ in) {
    const int t   = threadIdx.x;
    const int m   = t >> 5;          // warp id = m-tile (0..11)
    const int lid = t & 31;
    const int g   = lid >> 2;        // 0..7
    const int tg  = lid & 3;         // 0..3
    const int h   = blockIdx.x, b = blockIdx.y;

    const float* x1 = in + (size_t)b * CHW + (size_t)h * WW;
    const float* x2 = x1 + X2OFF;

    const int wA = 16 * m + g;
    const float* pA = x1 + (size_t)(2 * tg) * HWs + wA;

    const float* pB[5];
    bool predB[5];
    #pragma unroll
    for (int tt = 0; tt < 5; tt++) {
        int n = 8 * (2 * m + tt) + g;
        int j = n - 24;                      // x2 column; <0 -> zero pad
        predB[tt] = (j >= 0);
        pB[tt] = x2 + (size_t)(2 * tg) * HWs + (j >= 0 ? j : 0);
    }

    float acc[5][4];
    #pragma unroll
    for (int tt = 0; tt < 5; tt++)
        #pragma unroll
        for (int q = 0; q < 4; q++) acc[tt][q] = 0.f;

    #pragma unroll 2
    for (int ks = 0; ks < 16; ks++) {
        uint32_t Ah[4], Al[4];
        // a0:(c0,w) (c0+1,w) | a1:(c0,w+8) | a2:(c0+8,w) | a3:(c0+8,w+8)
        split2(__ldg(pA),               __ldg(pA + HWs),         Ah[0], Al[0]);
        split2(__ldg(pA + 8),           __ldg(pA + HWs + 8),     Ah[1], Al[1]);
        split2(__ldg(pA + 8 * HWs),     __ldg(pA + 9 * HWs),     Ah[2], Al[2]);
        split2(__ldg(pA + 8 * HWs + 8), __ldg(pA + 9 * HWs + 8), Ah[3], Al[3]);
        pA += 16 * (size_t)HWs;

        #pragma unroll
        for (int tt = 0; tt < 5; tt++) {
            const float* p = pB[tt];
            bool pr = predB[tt];
            float f0 = pr ? __ldg(p)               : 0.f;   // b0.lo (k=2tg)
            float f1 = pr ? __ldg(p + HWs)         : 0.f;   // b0.hi (k=2tg+1)
            float f2 = pr ? __ldg(p + 8 * HWs)     : 0.f;   // b1.lo (k=2tg+8)
            float f3 = pr ? __ldg(p + 9 * HWs)     : 0.f;   // b1.hi
            uint32_t Bh[2], Bl[2];
            split2(f0, f1, Bh[0], Bl[0]);
            split2(f2, f3, Bh[1], Bl[1]);
            mma_bf16(acc[tt], Ah, Bh);   // hi*hi
            mma_bf16(acc[tt], Al, Bh);   // lo*hi
            mma_bf16(acc[tt], Ah, Bl);   // hi*lo
            pB[tt] += 16 * (size_t)HWs;
        }
    }

    // epilogue: band-predicated scatter. c0:(g,2tg) c1:(g,2tg+1) c2:(g+8,2tg) c3:(g+8,2tg+1)
    #pragma unroll
    for (int tt = 0; tt < 5; tt++) {
        int n0 = 8 * (2 * m + tt) + 2 * tg;
        #pragma unroll
        for (int q = 0; q < 4; q++) {
            int w = wA + ((q >= 2) ? 8 : 0);
            int n = n0 + (q & 1);
            int d = w + 24 - n;
            if (d >= 0 && d < DD)
                g_corr[(((size_t)b * DD + d) * HH + h) * WW + w] = acc[tt][q];
        }
    }
}

// ---------------- box: whole-plane 3x3 box sum (unchanged, 10.5us) ----------------
#define BSTR 200
#define TPB2 192
__global__ __launch_bounds__(TPB2)
void box_kernel(float* __restrict__ out) {
    __shared__ float s[66 * BSTR];
    const int t = threadIdx.x, plane = blockIdx.x;
    const float* cp = g_corr + (size_t)plane * HWs;
    float*       op = out    + (size_t)plane * HWs;

    for (int i = t; i < 2 * 194; i += TPB2) {
        int r = (i < 194) ? 0 : 65;
        int c = (i < 194 ? i : i - 194) + 3;
        s[r * BSTR + c] = 0.f;
    }
    if (t < 64) { s[(t + 1) * BSTR + 3] = 0.f; s[(t + 1) * BSTR + 196] = 0.f; }
    #pragma unroll
    for (int k = 0; k < 16; k++) {
        int idx = t + k * TPB2;
        int row = idx / 48, c4 = idx - row * 48;
        float4 v = __ldg((const float4*)(cp + row * WW + c4 * 4));
        *((float4*)&s[(row + 1) * BSTR + 4 + c4 * 4]) = v;
    }
    __syncthreads();
    const float* col = &s[4 + t];
    float hsA = 0.f;
    float hsB = col[BSTR - 1] + col[BSTR] + col[BSTR + 1];
    #pragma unroll 4
    for (int h = 0; h < HH; h++) {
        const float* p = &col[(h + 2) * BSTR];
        float hsC = p[-1] + p[0] + p[1];
        op[h * WW + t] = hsA + hsB + hsC;
        hsA = hsB; hsB = hsC;
    }
}

extern "C" void kernel_launch(void* const* d_in, const int* in_sizes, int n_in,
                              void* d_out, int out_size) {
    const float* in = (const float*)d_in[0];
    float* out = (float*)d_out;

    dim3 g1(HH, BB);                 // 1024 CTAs, one per (b,h)
    corr_mma<<<g1, 384>>>(in);

    box_kernel<<<BB * DD, TPB2>>>(out);   // 400 planes
}

// round 9
// speedup vs baseline: 1.5178x; 1.5178x over previous
#include <cuda_runtime.h>
#include <cstdint>

#define BB   16
#define CC   256
#define HH   64
#define WW   192
#define DD   25
#define HWs  (HH*WW)
#define CHW  (512*HH*WW)
#define X2OFF ((size_t)CC*HWs)

// smem staging geometry (floats)
#define S1    196                 // x1 row stride  (196 % 16 == 4 -> conflict-free frag LDS)
#define S2    228                 // x2 row stride  (24-col zero front pad + 192 data)
#define X1F   (16*S1)             // x2 region offset inside a buffer: 3136
#define BUFF  (16*S1 + 16*S2)     // 6784 floats per buffer
#define NBUF  3
#define SMEM_BYTES (NBUF*BUFF*4)  // 81408

__device__ float g_corr[(size_t)BB*DD*HH*WW];

__device__ __forceinline__ uint32_t smem_u32(const void* p) {
    uint32_t a;
    asm("{ .reg .u64 t; cvta.to.shared.u64 t, %1; cvt.u32.u64 %0, t; }" : "=r"(a) : "l"(p));
    return a;
}
__device__ __forceinline__ void cp_async16(uint32_t dst, const void* src) {
    asm volatile("cp.async.cg.shared.global [%0], [%1], 16;\n" :: "r"(dst), "l"(src));
}
// split f0,f1 into packed bf16x2 hi and lo (lo16 of reg = f0, hi16 = f1)
__device__ __forceinline__ void split2(float f0, float f1, uint32_t& hi, uint32_t& lo) {
    asm("cvt.rn.bf16x2.f32 %0, %1, %2;" : "=r"(hi) : "f"(f1), "f"(f0));
    float l0 = f0 - __uint_as_float(hi << 16);
    float l1 = f1 - __uint_as_float(hi & 0xffff0000u);
    asm("cvt.rn.bf16x2.f32 %0, %1, %2;" : "=r"(lo) : "f"(l1), "f"(l0));
}
__device__ __forceinline__ void mma_bf16(float* d, const uint32_t* a, const uint32_t* b) {
    asm volatile("mma.sync.aligned.m16n8k16.row.col.f32.bf16.bf16.f32 "
        "{%0,%1,%2,%3}, {%4,%5,%6,%7}, {%8,%9}, {%0,%1,%2,%3};"
        : "+f"(d[0]), "+f"(d[1]), "+f"(d[2]), "+f"(d[3])
        : "r"(a[0]), "r"(a[1]), "r"(a[2]), "r"(a[3]), "r"(b[0]), "r"(b[1]));
}

// D[w][n] = sum_c x1[c][w] * x2pad[c][n], n = w + 24 - d.  CTA per (b,h), warp m: w-tile [16m,16m+16).
__global__ void __launch_bounds__(384, 2) corr_mma(const float* __restrict__ in) {
    extern __shared__ float sm[];

    const int t   = threadIdx.x;
    const int m   = t >> 5;
    const int lid = t & 31;
    const int g   = lid >> 2;
    const int tg  = lid & 3;
    const int h   = blockIdx.x, b = blockIdx.y;

    const float* x1 = in + (size_t)b * CHW + (size_t)h * WW;
    const float* x2 = x1 + X2OFF;

    // zero the 24-col front pads of all 3 buffers (16 rows each) once
    for (int i = t; i < NBUF * 16 * 24; i += 384) {
        int bu  = i / (16 * 24);
        int rem = i - bu * 16 * 24;
        int row = rem / 24, col = rem - row * 24;
        sm[bu * BUFF + X1F + row * S2 + col] = 0.f;
    }

    // staging map: slots 0,1 -> x1 rows t/48, (t+384)/48 ; slots 2,3 -> x2 same rows
    const int r0 = t / 48,          c40 = t - r0 * 48;
    const int r1 = (t + 384) / 48,  c41 = (t + 384) - r1 * 48;
    const size_t so0 = (size_t)r0 * HWs + c40 * 4;
    const size_t so1 = (size_t)r1 * HWs + c41 * 4;
    const uint32_t smbase = smem_u32(sm);
    const uint32_t d0 = smbase + (r0 * S1 + c40 * 4) * 4;
    const uint32_t d1 = smbase + (r1 * S1 + c41 * 4) * 4;
    const uint32_t d2 = smbase + (X1F + r0 * S2 + 24 + c40 * 4) * 4;
    const uint32_t d3 = smbase + (X1F + r1 * S2 + 24 + c41 * 4) * 4;

#define ISSUE(buf, ch) do {                                                    \
    const size_t _co = (size_t)(ch) * 16 * HWs;                                \
    const uint32_t _bo = (buf) * (BUFF * 4);                                   \
    cp_async16(d0 + _bo, x1 + _co + so0);                                      \
    cp_async16(d1 + _bo, x1 + _co + so1);                                      \
    cp_async16(d2 + _bo, x2 + _co + so0);                                      \
    cp_async16(d3 + _bo, x2 + _co + so1);                                      \
    asm volatile("cp.async.commit_group;\n");                                  \
} while (0)

    float acc[5][4];
    #pragma unroll
    for (int tt = 0; tt < 5; tt++)
        #pragma unroll
        for (int q = 0; q < 4; q++) acc[tt][q] = 0.f;

    const int wA = 16 * m + g;   // A w-column
    const int k0 = 2 * tg;       // A/B k-row base

    ISSUE(0, 0);
    ISSUE(1, 1);

    int buf = 0;
    #pragma unroll 1
    for (int ch = 0; ch < 16; ch++) {
        if (ch < 15) asm volatile("cp.async.wait_group 1;\n");
        else         asm volatile("cp.async.wait_group 0;\n");
        __syncthreads();
        if (ch + 2 < 16) {
            int nb = buf + 2; if (nb >= NBUF) nb -= NBUF;
            ISSUE(nb, ch + 2);
        }

        const int X1B = buf * BUFF;
        const int X2B = buf * BUFF + X1F;

        // A fragments (k16): rows k0,k0+1 (+8), cols wA, wA+8
        uint32_t Ah[4], Al[4];
        split2(sm[X1B + k0 * S1 + wA],           sm[X1B + (k0 + 1) * S1 + wA],           Ah[0], Al[0]);
        split2(sm[X1B + k0 * S1 + wA + 8],       sm[X1B + (k0 + 1) * S1 + wA + 8],       Ah[1], Al[1]);
        split2(sm[X1B + (k0 + 8) * S1 + wA],     sm[X1B + (k0 + 9) * S1 + wA],           Ah[2], Al[2]);
        split2(sm[X1B + (k0 + 8) * S1 + wA + 8], sm[X1B + (k0 + 9) * S1 + wA + 8],       Ah[3], Al[3]);

        #pragma unroll
        for (int tt = 0; tt < 5; tt++) {
            const int nB = 16 * m + 8 * tt + g;   // padded x2 col 0..215
            uint32_t Bh[2], Bl[2];
            split2(sm[X2B + k0 * S2 + nB],       sm[X2B + (k0 + 1) * S2 + nB], Bh[0], Bl[0]);
            split2(sm[X2B + (k0 + 8) * S2 + nB], sm[X2B + (k0 + 9) * S2 + nB], Bh[1], Bl[1]);
            mma_bf16(acc[tt], Ah, Bh);
            mma_bf16(acc[tt], Al, Bh);
            mma_bf16(acc[tt], Ah, Bl);
        }
        if (++buf >= NBUF) buf = 0;
    }
#undef ISSUE

    // epilogue: band-predicated scatter (proven R8)
    #pragma unroll
    for (int tt = 0; tt < 5; tt++) {
        int n0 = 8 * (2 * m + tt) + 2 * tg;
        #pragma unroll
        for (int q = 0; q < 4; q++) {
            int w = wA + ((q >= 2) ? 8 : 0);
            int n = n0 + (q & 1);
            int d = w + 24 - n;
            if (d >= 0 && d < DD)
                g_corr[(((size_t)b * DD + d) * HH + h) * WW + w] = acc[tt][q];
        }
    }
}

// ---------------- box: half-plane 3x3 box sum ----------------
#define BSTR 200
#define TPB2 192
__global__ __launch_bounds__(TPB2)
void box_kernel(float* __restrict__ out) {
    __shared__ float s[34 * BSTR];   // 27.2 KB

    const int t     = threadIdx.x;   // w column
    const int plane = blockIdx.x;    // b*25+d
    const int h0    = blockIdx.y * 32;

    const float* cp = g_corr + (size_t)plane * HWs;
    float*       op = out    + (size_t)plane * HWs;

    if (t < 34) { s[t * BSTR + 3] = 0.f; s[t * BSTR + 196] = 0.f; }
    #pragma unroll
    for (int k = 0; k < 9; k++) {
        int idx = t + k * TPB2;            // 34*48 = 1632 float4s
        if (idx < 1632) {
            int row = idx / 48, c4 = idx - row * 48;
            int hh = h0 + row - 1;
            float4 v = make_float4(0.f, 0.f, 0.f, 0.f);
            if (hh >= 0 && hh < HH) v = __ldg((const float4*)(cp + hh * WW + c4 * 4));
            *((float4*)&s[row * BSTR + 4 + c4 * 4]) = v;
        }
    }
    __syncthreads();

    const float* col = &s[4 + t];
    float hsA = col[-1] + col[0] + col[1];                          // smem row 0 (h0-1)
    float hsB = col[BSTR - 1] + col[BSTR] + col[BSTR + 1];          // row 1 (h0)
    #pragma unroll 4
    for (int r = 0; r < 32; r++) {
        const float* p = &col[(r + 2) * BSTR];
        float hsC = p[-1] + p[0] + p[1];
        op[(h0 + r) * WW + t] = hsA + hsB + hsC;
        hsA = hsB; hsB = hsC;
    }
}

extern "C" void kernel_launch(void* const* d_in, const int* in_sizes, int n_in,
                              void* d_out, int out_size) {
    const float* in = (const float*)d_in[0];
    float* out = (float*)d_out;

    cudaFuncSetAttribute(corr_mma, cudaFuncAttributeMaxDynamicSharedMemorySize, SMEM_BYTES);
    dim3 g1(HH, BB);                    // 1024 CTAs
    corr_mma<<<g1, 384, SMEM_BYTES>>>(in);

    dim3 g2(BB * DD, 2);                // 800 blocks
    box_kernel<<<g2, TPB2>>>(out);
}

// round 10
// speedup vs baseline: 1.5472x; 1.0194x over previous
#include <cuda_runtime.h>
#include <cstdint>

#define BB   16
#define CC   256
#define HH   64
#define WW   192
#define DD   25
#define HWs  (HH*WW)
#define CHW  (512*HH*WW)
#define X2OFF ((size_t)CC*HWs)

// smem staging geometry (floats)
#define S1    196                 // x1 row stride (conflict-free frag LDS)
#define S2    228                 // x2 row stride (24-col zero front pad + 192 data)
#define X1F   (16*S1)
#define BUFF  (16*S1 + 16*S2)     // 6784 floats
#define NBUF  4
#define SMEM_BYTES (NBUF*BUFF*4)  // 108544

__device__ float g_corr[(size_t)BB*DD*HH*WW];

__device__ __forceinline__ uint32_t smem_u32(const void* p) {
    uint32_t a;
    asm("{ .reg .u64 t; cvta.to.shared.u64 t, %1; cvt.u32.u64 %0, t; }" : "=r"(a) : "l"(p));
    return a;
}
__device__ __forceinline__ void cp_async16(uint32_t dst, const void* src) {
    asm volatile("cp.async.cg.shared.global [%0], [%1], 16;\n" :: "r"(dst), "l"(src));
}
// split f0,f1 into packed bf16x2 hi and lo (lo16 of reg = f0, hi16 = f1)
__device__ __forceinline__ void split2(float f0, float f1, uint32_t& hi, uint32_t& lo) {
    asm("cvt.rn.bf16x2.f32 %0, %1, %2;" : "=r"(hi) : "f"(f1), "f"(f0));
    float l0 = f0 - __uint_as_float(hi << 16);
    float l1 = f1 - __uint_as_float(hi & 0xffff0000u);
    asm("cvt.rn.bf16x2.f32 %0, %1, %2;" : "=r"(lo) : "f"(l1), "f"(l0));
}
__device__ __forceinline__ void mma_bf16(float* d, const uint32_t* a, const uint32_t* b) {
    asm volatile("mma.sync.aligned.m16n8k16.row.col.f32.bf16.bf16.f32 "
        "{%0,%1,%2,%3}, {%4,%5,%6,%7}, {%8,%9}, {%0,%1,%2,%3};"
        : "+f"(d[0]), "+f"(d[1]), "+f"(d[2]), "+f"(d[3])
        : "r"(a[0]), "r"(a[1]), "r"(a[2]), "r"(a[3]), "r"(b[0]), "r"(b[1]));
}

// D[w][n] = sum_c x1[c][w] * x2pad[c][n], n = w + 24 - d.  CTA per (b,h), warp m: w-tile [16m,16m+16).
__global__ void __launch_bounds__(384, 2) corr_mma(const float* __restrict__ in) {
    extern __shared__ float sm[];

    const int t   = threadIdx.x;
    const int m   = t >> 5;
    const int lid = t & 31;
    const int g   = lid >> 2;
    const int tg  = lid & 3;
    const int h   = blockIdx.x, b = blockIdx.y;

    const float* x1 = in + (size_t)b * CHW + (size_t)h * WW;
    const float* x2 = x1 + X2OFF;

    // zero the 24-col front pads of all buffers once
    for (int i = t; i < NBUF * 16 * 24; i += 384) {
        int bu  = i / (16 * 24);
        int rem = i - bu * 16 * 24;
        int row = rem / 24, col = rem - row * 24;
        sm[bu * BUFF + X1F + row * S2 + col] = 0.f;
    }

    // staging map: 2 float4 rows of x1 + 2 of x2 per thread per chunk
    const int r0 = t / 48,          c40 = t - r0 * 48;
    const int r1 = (t + 384) / 48,  c41 = (t + 384) - r1 * 48;
    const size_t so0 = (size_t)r0 * HWs + c40 * 4;
    const size_t so1 = (size_t)r1 * HWs + c41 * 4;
    const uint32_t smbase = smem_u32(sm);
    const uint32_t d0 = smbase + (r0 * S1 + c40 * 4) * 4;
    const uint32_t d1 = smbase + (r1 * S1 + c41 * 4) * 4;
    const uint32_t d2 = smbase + (X1F + r0 * S2 + 24 + c40 * 4) * 4;
    const uint32_t d3 = smbase + (X1F + r1 * S2 + 24 + c41 * 4) * 4;

#define ISSUE(buf, ch) do {                                                    \
    const size_t _co = (size_t)(ch) * 16 * HWs;                                \
    const uint32_t _bo = (buf) * (BUFF * 4);                                   \
    cp_async16(d0 + _bo, x1 + _co + so0);                                      \
    cp_async16(d1 + _bo, x1 + _co + so1);                                      \
    cp_async16(d2 + _bo, x2 + _co + so0);                                      \
    cp_async16(d3 + _bo, x2 + _co + so1);                                      \
    asm volatile("cp.async.commit_group;\n");                                  \
} while (0)

    float acc[5][4];
    #pragma unroll
    for (int tt = 0; tt < 5; tt++)
        #pragma unroll
        for (int q = 0; q < 4; q++) acc[tt][q] = 0.f;

    const int wA = 16 * m + g;
    const int k0 = 2 * tg;

    ISSUE(0, 0);
    ISSUE(1, 1);
    ISSUE(2, 2);

    int buf = 0;
    #pragma unroll 1
    for (int ch = 0; ch < 16; ch++) {
        if (ch < 14)      asm volatile("cp.async.wait_group 2;\n");
        else if (ch < 15) asm volatile("cp.async.wait_group 1;\n");
        else              asm volatile("cp.async.wait_group 0;\n");
        __syncthreads();
        if (ch + 3 < 16) {
            int nb = buf + 3; if (nb >= NBUF) nb -= NBUF;
            ISSUE(nb, ch + 3);
        }

        const int X1B = buf * BUFF;
        const int X2B = buf * BUFF + X1F;

        uint32_t Ah[4], Al[4];
        split2(sm[X1B + k0 * S1 + wA],           sm[X1B + (k0 + 1) * S1 + wA],     Ah[0], Al[0]);
        split2(sm[X1B + k0 * S1 + wA + 8],       sm[X1B + (k0 + 1) * S1 + wA + 8], Ah[1], Al[1]);
        split2(sm[X1B + (k0 + 8) * S1 + wA],     sm[X1B + (k0 + 9) * S1 + wA],     Ah[2], Al[2]);
        split2(sm[X1B + (k0 + 8) * S1 + wA + 8], sm[X1B + (k0 + 9) * S1 + wA + 8], Ah[3], Al[3]);

        #pragma unroll
        for (int tt = 0; tt < 5; tt++) {
            const int nB = 16 * m + 8 * tt + g;   // padded x2 col
            uint32_t Bh[2], Bl[2];
            split2(sm[X2B + k0 * S2 + nB],       sm[X2B + (k0 + 1) * S2 + nB], Bh[0], Bl[0]);
            split2(sm[X2B + (k0 + 8) * S2 + nB], sm[X2B + (k0 + 9) * S2 + nB], Bh[1], Bl[1]);
            mma_bf16(acc[tt], Ah, Bh);
            mma_bf16(acc[tt], Al, Bh);
            mma_bf16(acc[tt], Ah, Bl);
        }
        if (++buf >= NBUF) buf = 0;
    }
#undef ISSUE

    // epilogue: band-predicated scatter
    #pragma unroll
    for (int tt = 0; tt < 5; tt++) {
        int n0 = 8 * (2 * m + tt) + 2 * tg;
        #pragma unroll
        for (int q = 0; q < 4; q++) {
            int w = wA + ((q >= 2) ? 8 : 0);
            int n = n0 + (q & 1);
            int d = w + 24 - n;
            if (d >= 0 && d < DD)
                g_corr[(((size_t)b * DD + d) * HH + h) * WW + w] = acc[tt][q];
        }
    }
}

// ---------------- box: quarter-plane 3x3 box sum ----------------
#define BSTR  200
#define TPB2  192
#define QROWS 16

__global__ __launch_bounds__(TPB2)
void box_kernel(float* __restrict__ out) {
    __shared__ float s[(QROWS + 2) * BSTR];   // 18*200*4 = 14.4 KB

    const int t     = threadIdx.x;   // w column
    const int plane = blockIdx.x;    // b*25+d
    const int h0    = blockIdx.y * QROWS;

    const float* cp = g_corr + (size_t)plane * HWs;
    float*       op = out    + (size_t)plane * HWs;

    if (t < QROWS + 2) { s[t * BSTR + 3] = 0.f; s[t * BSTR + 196] = 0.f; }
    #pragma unroll
    for (int k = 0; k < 5; k++) {
        int idx = t + k * TPB2;                 // (QROWS+2)*48 = 864 float4s
        if (idx < (QROWS + 2) * 48) {
            int row = idx / 48, c4 = idx - row * 48;
            int hh = h0 + row - 1;
            float4 v = make_float4(0.f, 0.f, 0.f, 0.f);
            if (hh >= 0 && hh < HH) v = __ldg((const float4*)(cp + hh * WW + c4 * 4));
            *((float4*)&s[row * BSTR + 4 + c4 * 4]) = v;
        }
    }
    __syncthreads();

    const float* col = &s[4 + t];
    float hsA = col[-1] + col[0] + col[1];                   // row h0-1
    float hsB = col[BSTR - 1] + col[BSTR] + col[BSTR + 1];   // row h0
    #pragma unroll
    for (int r = 0; r < QROWS; r++) {
        const float* p = &col[(r + 2) * BSTR];
        float hsC = p[-1] + p[0] + p[1];
        op[(h0 + r) * WW + t] = hsA + hsB + hsC;
        hsA = hsB; hsB = hsC;
    }
}

extern "C" void kernel_launch(void* const* d_in, const int* in_sizes, int n_in,
                              void* d_out, int out_size) {
    const float* in = (const float*)d_in[0];
    float* out = (float*)d_out;

    cudaFuncSetAttribute(corr_mma, cudaFuncAttributeMaxDynamicSharedMemorySize, SMEM_BYTES);
    dim3 g1(HH, BB);                    // 1024 CTAs
    corr_mma<<<g1, 384, SMEM_BYTES>>>(in);

    dim3 g2(BB * DD, HH / QROWS);       // (400, 4) = 1600 blocks
    box_kernel<<<g2, TPB2>>>(out);
}

// round 11
// speedup vs baseline: 1.5657x; 1.0120x over previous
#include <cuda_runtime.h>
#include <cstdint>

#define BB   16
#define CC   256
#define HH   64
#define WW   192
#define DD   25
#define HWs  (HH*WW)
#define CHW  (512*HH*WW)
#define X2OFF ((size_t)CC*HWs)

// smem staging geometry (floats)
#define S1    196                 // x1 row stride (conflict-free frag LDS)
#define S2    228                 // x2 row stride (24-col zero front pad + 192 data)
#define X1F   (16*S1)
#define BUFF  (16*S1 + 16*S2)     // 6784 floats
#define NBUF  4
#define SMEM_BYTES (NBUF*BUFF*4)  // 108544
#define SLABW 196                 // epilogue slab stride: banks (5g-8tg+c)%32 all distinct

__device__ float g_corr[(size_t)BB*DD*HH*WW];

__device__ __forceinline__ uint32_t smem_u32(const void* p) {
    uint32_t a;
    asm("{ .reg .u64 t; cvta.to.shared.u64 t, %1; cvt.u32.u64 %0, t; }" : "=r"(a) : "l"(p));
    return a;
}
__device__ __forceinline__ void cp_async16(uint32_t dst, const void* src) {
    asm volatile("cp.async.cg.shared.global [%0], [%1], 16;\n" :: "r"(dst), "l"(src));
}
// split f0,f1 into packed bf16x2 hi and lo (lo16 of reg = f0, hi16 = f1)
__device__ __forceinline__ void split2(float f0, float f1, uint32_t& hi, uint32_t& lo) {
    asm("cvt.rn.bf16x2.f32 %0, %1, %2;" : "=r"(hi) : "f"(f1), "f"(f0));
    float l0 = f0 - __uint_as_float(hi << 16);
    float l1 = f1 - __uint_as_float(hi & 0xffff0000u);
    asm("cvt.rn.bf16x2.f32 %0, %1, %2;" : "=r"(lo) : "f"(l1), "f"(l0));
}
__device__ __forceinline__ void mma_bf16(float* d, const uint32_t* a, const uint32_t* b) {
    asm volatile("mma.sync.aligned.m16n8k16.row.col.f32.bf16.bf16.f32 "
        "{%0,%1,%2,%3}, {%4,%5,%6,%7}, {%8,%9}, {%0,%1,%2,%3};"
        : "+f"(d[0]), "+f"(d[1]), "+f"(d[2]), "+f"(d[3])
        : "r"(a[0]), "r"(a[1]), "r"(a[2]), "r"(a[3]), "r"(b[0]), "r"(b[1]));
}

// D[w][n] = sum_c x1[c][w] * x2pad[c][n], n = w + 24 - d.  CTA per (b,h), warp m: w-tile [16m,16m+16).
__global__ void __launch_bounds__(384, 2) corr_mma(const float* __restrict__ in) {
    extern __shared__ float sm[];

    const int t   = threadIdx.x;
    const int m   = t >> 5;
    const int lid = t & 31;
    const int g   = lid >> 2;
    const int tg  = lid & 3;
    const int h   = blockIdx.x, b = blockIdx.y;

    const float* x1 = in + (size_t)b * CHW + (size_t)h * WW;
    const float* x2 = x1 + X2OFF;

    // zero the 24-col front pads of all buffers once
    for (int i = t; i < NBUF * 16 * 24; i += 384) {
        int bu  = i / (16 * 24);
        int rem = i - bu * 16 * 24;
        int row = rem / 24, col = rem - row * 24;
        sm[bu * BUFF + X1F + row * S2 + col] = 0.f;
    }

    // staging map: 2 float4 rows of x1 + 2 of x2 per thread per chunk
    const int r0 = t / 48,          c40 = t - r0 * 48;
    const int r1 = (t + 384) / 48,  c41 = (t + 384) - r1 * 48;
    const size_t so0 = (size_t)r0 * HWs + c40 * 4;
    const size_t so1 = (size_t)r1 * HWs + c41 * 4;
    const uint32_t smbase = smem_u32(sm);
    const uint32_t d0 = smbase + (r0 * S1 + c40 * 4) * 4;
    const uint32_t d1 = smbase + (r1 * S1 + c41 * 4) * 4;
    const uint32_t d2 = smbase + (X1F + r0 * S2 + 24 + c40 * 4) * 4;
    const uint32_t d3 = smbase + (X1F + r1 * S2 + 24 + c41 * 4) * 4;

#define ISSUE(buf, ch) do {                                                    \
    const size_t _co = (size_t)(ch) * 16 * HWs;                                \
    const uint32_t _bo = (buf) * (BUFF * 4);                                   \
    cp_async16(d0 + _bo, x1 + _co + so0);                                      \
    cp_async16(d1 + _bo, x1 + _co + so1);                                      \
    cp_async16(d2 + _bo, x2 + _co + so0);                                      \
    cp_async16(d3 + _bo, x2 + _co + so1);                                      \
    asm volatile("cp.async.commit_group;\n");                                  \
} while (0)

    float acc[5][4];
    #pragma unroll
    for (int tt = 0; tt < 5; tt++)
        #pragma unroll
        for (int q = 0; q < 4; q++) acc[tt][q] = 0.f;

    const int wA = 16 * m + g;
    const int k0 = 2 * tg;

    ISSUE(0, 0);
    ISSUE(1, 1);
    ISSUE(2, 2);

    int buf = 0;
    #pragma unroll 1
    for (int ch = 0; ch < 16; ch++) {
        if (ch < 14)      asm volatile("cp.async.wait_group 2;\n");
        else if (ch < 15) asm volatile("cp.async.wait_group 1;\n");
        else              asm volatile("cp.async.wait_group 0;\n");
        __syncthreads();
        if (ch + 3 < 16) {
            int nb = buf + 3; if (nb >= NBUF) nb -= NBUF;
            ISSUE(nb, ch + 3);
        }

        const int X1B = buf * BUFF;
        const int X2B = buf * BUFF + X1F;

        uint32_t Ah[4], Al[4];
        split2(sm[X1B + k0 * S1 + wA],           sm[X1B + (k0 + 1) * S1 + wA],     Ah[0], Al[0]);
        split2(sm[X1B + k0 * S1 + wA + 8],       sm[X1B + (k0 + 1) * S1 + wA + 8], Ah[1], Al[1]);
        split2(sm[X1B + (k0 + 8) * S1 + wA],     sm[X1B + (k0 + 9) * S1 + wA],     Ah[2], Al[2]);
        split2(sm[X1B + (k0 + 8) * S1 + wA + 8], sm[X1B + (k0 + 9) * S1 + wA + 8], Ah[3], Al[3]);

        #pragma unroll
        for (int tt = 0; tt < 5; tt++) {
            const int nB = 16 * m + 8 * tt + g;   // padded x2 col
            uint32_t Bh[2], Bl[2];
            split2(sm[X2B + k0 * S2 + nB],       sm[X2B + (k0 + 1) * S2 + nB], Bh[0], Bl[0]);
            split2(sm[X2B + (k0 + 8) * S2 + nB], sm[X2B + (k0 + 9) * S2 + nB], Bh[1], Bl[1]);
            mma_bf16(acc[tt], Ah, Bh);
            mma_bf16(acc[tt], Al, Bh);
            mma_bf16(acc[tt], Ah, Bl);
        }
        if (++buf >= NBUF) buf = 0;
    }
#undef ISSUE

    // epilogue: scatter accs into smem slab [25][SLABW] (conflict-free), then coalesced STG.
    // Slab sits in buffer 0 region (<= 4900 floats < BUFF); last chunk computes from buffer 3,
    // so regions are disjoint — no extra sync needed before slab writes.
    float* slab = sm;
    #pragma unroll
    for (int tt = 0; tt < 5; tt++) {
        int n0 = 8 * (2 * m + tt) + 2 * tg;
        #pragma unroll
        for (int q = 0; q < 4; q++) {
            int w = wA + ((q >= 2) ? 8 : 0);
            int n = n0 + (q & 1);
            int d = w + 24 - n;
            if (d >= 0 && d < DD)
                slab[d * SLABW + w] = acc[tt][q];
        }
    }
    __syncthreads();
    {
        const size_t pb = ((size_t)b * DD * HH + h) * WW;   // (b, d=0, h, 0)
        #pragma unroll 1
        for (int idx = t; idx < DD * 48; idx += 384) {
            int d  = idx / 48;
            int c4 = idx - d * 48;
            float4 v = *(float4*)&slab[d * SLABW + c4 * 4];
            *(float4*)(g_corr + pb + (size_t)d * HWs + c4 * 4) = v;
        }
    }
}

// ---------------- box: no-sync direct 3x3 box sum, one float4 per thread ----------------
#define TPB2 256

__global__ __launch_bounds__(TPB2)
void box_kernel(float* __restrict__ out) {
    const int plane = blockIdx.y;                       // b*25 + d
    const int o4 = blockIdx.x * TPB2 + threadIdx.x;     // float4 slot in plane: 0..3071
    const int h  = o4 / 48;
    const int c4 = o4 - h * 48;
    const int w0 = c4 * 4;

    const float* cp = g_corr + (size_t)plane * HWs;

    float s0 = 0.f, s1 = 0.f, s2 = 0.f, s3 = 0.f, s4 = 0.f, s5 = 0.f;
    #pragma unroll
    for (int r = -1; r <= 1; r++) {
        int hh = h + r;
        if (hh >= 0 && hh < HH) {
            const float* rp = cp + hh * WW;
            float4 v = __ldg((const float4*)(rp + w0));
            s1 += v.x; s2 += v.y; s3 += v.z; s4 += v.w;
            if (w0 > 0)   s0 += __ldg(rp + w0 - 1);
            if (w0 < 188) s5 += __ldg(rp + w0 + 4);
        }
    }
    float4 o;
    o.x = s0 + s1 + s2;
    o.y = s1 + s2 + s3;
    o.z = s2 + s3 + s4;
    o.w = s3 + s4 + s5;
    *(float4*)(out + (size_t)plane * HWs + h * WW + w0) = o;
}

extern "C" void kernel_launch(void* const* d_in, const int* in_sizes, int n_in,
                              void* d_out, int out_size) {
    const float* in = (const float*)d_in[0];
    float* out = (float*)d_out;

    cudaFuncSetAttribute(corr_mma, cudaFuncAttributeMaxDynamicSharedMemorySize, SMEM_BYTES);
    dim3 g1(HH, BB);                    // 1024 CTAs
    corr_mma<<<g1, 384, SMEM_BYTES>>>(in);

    dim3 g2(12, BB * DD);               // 4800 blocks, 256 thr: one float4 per thread
    box_kernel<<<g2, TPB2>>>(out);
}

// round 13
// speedup vs baseline: 1.6120x; 1.0295x over previous
#include <cuda_runtime.h>
#include <cstdint>

#define BB   16
#define CC   256
#define HH   64
#define WW   192
#define DD   25
#define HWs  (HH*WW)
#define CHW  (512*HH*WW)
#define X2OFF ((size_t)CC*HWs)

// smem staging geometry (floats)
#define S1    196                 // x1 row stride (conflict-free frag LDS)
#define S2    228                 // x2 row stride (24-col zero front pad + 192 data)
#define X1F   (16*S1)
#define BUFF  (16*S1 + 16*S2)     // 6784 floats
#define NBUF  4
#define SMEM_BYTES (NBUF*BUFF*4)  // 108544
// epilogue slab: stride 196, data at cols 4..195 (16B-aligned), zero pads at col 3
// and col 196 (col 196 of row d aliases unused cols 0..2 region of row d+1).
#define SLABW 196

// g_hs[b][d][h][w] = horizontal 3-sum of corr
__device__ float g_hs[(size_t)BB*DD*HH*WW];

__device__ __forceinline__ uint32_t smem_u32(const void* p) {
    uint32_t a;
    asm("{ .reg .u64 t; cvta.to.shared.u64 t, %1; cvt.u32.u64 %0, t; }" : "=r"(a) : "l"(p));
    return a;
}
__device__ __forceinline__ void cp_async16(uint32_t dst, const void* src) {
    asm volatile("cp.async.cg.shared.global [%0], [%1], 16;\n" :: "r"(dst), "l"(src));
}
// split f0,f1 into packed bf16x2 hi and lo (lo16 of reg = f0, hi16 = f1)
__device__ __forceinline__ void split2(float f0, float f1, uint32_t& hi, uint32_t& lo) {
    asm("cvt.rn.bf16x2.f32 %0, %1, %2;" : "=r"(hi) : "f"(f1), "f"(f0));
    float l0 = f0 - __uint_as_float(hi << 16);
    float l1 = f1 - __uint_as_float(hi & 0xffff0000u);
    asm("cvt.rn.bf16x2.f32 %0, %1, %2;" : "=r"(lo) : "f"(l1), "f"(l0));
}
__device__ __forceinline__ void mma_bf16(float* d, const uint32_t* a, const uint32_t* b) {
    asm volatile("mma.sync.aligned.m16n8k16.row.col.f32.bf16.bf16.f32 "
        "{%0,%1,%2,%3}, {%4,%5,%6,%7}, {%8,%9}, {%0,%1,%2,%3};"
        : "+f"(d[0]), "+f"(d[1]), "+f"(d[2]), "+f"(d[3])
        : "r"(a[0]), "r"(a[1]), "r"(a[2]), "r"(a[3]), "r"(b[0]), "r"(b[1]));
}

// D[w][n] = sum_c x1[c][w] * x2pad[c][n], n = w + 24 - d.  CTA per (b,h), warp m: w-tile [16m,16m+16).
__global__ void __launch_bounds__(384, 2) corr_mma(const float* __restrict__ in) {
    extern __shared__ float sm[];

    const int t   = threadIdx.x;
    const int m   = t >> 5;
    const int lid = t & 31;
    const int g   = lid >> 2;
    const int tg  = lid & 3;
    const int h   = blockIdx.x, b = blockIdx.y;

    const float* x1 = in + (size_t)b * CHW + (size_t)h * WW;
    const float* x2 = x1 + X2OFF;

    // zero the 24-col front pads of all buffers once
    for (int i = t; i < NBUF * 16 * 24; i += 384) {
        int bu  = i / (16 * 24);
        int rem = i - bu * 16 * 24;
        int row = rem / 24, col = rem - row * 24;
        sm[bu * BUFF + X1F + row * S2 + col] = 0.f;
    }

    // staging map: 2 float4 rows of x1 + 2 of x2 per thread per chunk
    const int r0 = t / 48,          c40 = t - r0 * 48;
    const int r1 = (t + 384) / 48,  c41 = (t + 384) - r1 * 48;
    const size_t so0 = (size_t)r0 * HWs + c40 * 4;
    const size_t so1 = (size_t)r1 * HWs + c41 * 4;
    const uint32_t smbase = smem_u32(sm);
    const uint32_t d0 = smbase + (r0 * S1 + c40 * 4) * 4;
    const uint32_t d1 = smbase + (r1 * S1 + c41 * 4) * 4;
    const uint32_t d2 = smbase + (X1F + r0 * S2 + 24 + c40 * 4) * 4;
    const uint32_t d3 = smbase + (X1F + r1 * S2 + 24 + c41 * 4) * 4;

#define ISSUE(buf, ch) do {                                                    \
    const size_t _co = (size_t)(ch) * 16 * HWs;                                \
    const uint32_t _bo = (buf) * (BUFF * 4);                                   \
    cp_async16(d0 + _bo, x1 + _co + so0);                                      \
    cp_async16(d1 + _bo, x1 + _co + so1);                                      \
    cp_async16(d2 + _bo, x2 + _co + so0);                                      \
    cp_async16(d3 + _bo, x2 + _co + so1);                                      \
    asm volatile("cp.async.commit_group;\n");                                  \
} while (0)

    float acc[5][4];
    #pragma unroll
    for (int tt = 0; tt < 5; tt++)
        #pragma unroll
        for (int q = 0; q < 4; q++) acc[tt][q] = 0.f;

    const int wA = 16 * m + g;
    const int k0 = 2 * tg;

    ISSUE(0, 0);
    ISSUE(1, 1);
    ISSUE(2, 2);

    int buf = 0;
    #pragma unroll 1
    for (int ch = 0; ch < 16; ch++) {
        if (ch < 14)      asm volatile("cp.async.wait_group 2;\n");
        else if (ch < 15) asm volatile("cp.async.wait_group 1;\n");
        else              asm volatile("cp.async.wait_group 0;\n");
        __syncthreads();
        if (ch + 3 < 16) {
            int nb = buf + 3; if (nb >= NBUF) nb -= NBUF;
            ISSUE(nb, ch + 3);
        }

        const int X1B = buf * BUFF;
        const int X2B = buf * BUFF + X1F;

        uint32_t Ah[4], Al[4];
        split2(sm[X1B + k0 * S1 + wA],           sm[X1B + (k0 + 1) * S1 + wA],     Ah[0], Al[0]);
        split2(sm[X1B + k0 * S1 + wA + 8],       sm[X1B + (k0 + 1) * S1 + wA + 8], Ah[1], Al[1]);
        split2(sm[X1B + (k0 + 8) * S1 + wA],     sm[X1B + (k0 + 9) * S1 + wA],     Ah[2], Al[2]);
        split2(sm[X1B + (k0 + 8) * S1 + wA + 8], sm[X1B + (k0 + 9) * S1 + wA + 8], Ah[3], Al[3]);

        #pragma unroll
        for (int tt = 0; tt < 5; tt++) {
            const int nB = 16 * m + 8 * tt + g;   // padded x2 col
            uint32_t Bh[2], Bl[2];
            split2(sm[X2B + k0 * S2 + nB],       sm[X2B + (k0 + 1) * S2 + nB], Bh[0], Bl[0]);
            split2(sm[X2B + (k0 + 8) * S2 + nB], sm[X2B + (k0 + 9) * S2 + nB], Bh[1], Bl[1]);
            mma_bf16(acc[tt], Ah, Bh);
            mma_bf16(acc[tt], Al, Bh);
            mma_bf16(acc[tt], Ah, Bl);
        }
        if (++buf >= NBUF) buf = 0;
    }
#undef ISSUE

    // epilogue: scatter accs into slab [25][SLABW] at col w+4 (conflict-free: bank
    // (5g-8tg+const)%32 pairwise distinct), zero pads at cols 3 and 196, then
    // horizontal 3-sum fused into the coalesced store.
    // Slab (~5100 floats) sits in buffer 0 region; last chunk used buffer 3 — disjoint.
    float* slab = sm;
    if (t < 2 * DD) {
        int d = t >> 1;
        slab[d * SLABW + ((t & 1) ? 196 : 3)] = 0.f;   // col196 aliases row d+1 cols<3 (unused)
    }
    #pragma unroll
    for (int tt = 0; tt < 5; tt++) {
        int n0 = 8 * (2 * m + tt) + 2 * tg;
        #pragma unroll
        for (int q = 0; q < 4; q++) {
            int w = wA + ((q >= 2) ? 8 : 0);
            int n = n0 + (q & 1);
            int d = w + 24 - n;
            if (d >= 0 && d < DD)
                slab[d * SLABW + 4 + w] = acc[tt][q];
        }
    }
    __syncthreads();
    {
        const size_t pb = ((size_t)b * DD * HH + h) * WW;   // (b, d=0, h, 0)
        #pragma unroll 1
        for (int idx = t; idx < DD * 48; idx += 384) {
            int d  = idx / 48;
            int c4 = idx - d * 48;
            const float* p = &slab[d * SLABW + 4 + c4 * 4];  // 16B aligned: 196%4==0
            float4 v = *(const float4*)p;
            float lft = p[-1], rgt = p[4];
            float4 hs;
            hs.x = lft + v.x + v.y;
            hs.y = v.x + v.y + v.z;
            hs.z = v.y + v.z + v.w;
            hs.w = v.z + v.w + rgt;
            *(float4*)(g_hs + pb + (size_t)d * HWs + c4 * 4) = hs;
        }
    }
}

// ---------------- box: pure vertical 3-sum over g_hs, one float4 per thread ----------------
#define TPB2 256

__global__ __launch_bounds__(TPB2)
void box_kernel(float* __restrict__ out) {
    const int plane = blockIdx.y;                       // b*25 + d
    const int o4 = blockIdx.x * TPB2 + threadIdx.x;     // float4 slot: 0..3071
    const int h  = o4 / 48;
    const int w0 = (o4 - h * 48) * 4;

    const float* hp = g_hs + (size_t)plane * HWs + h * WW + w0;

    float4 s = __ldg((const float4*)hp);
    if (h > 0) {
        float4 a = __ldg((const float4*)(hp - WW));
        s.x += a.x; s.y += a.y; s.z += a.z; s.w += a.w;
    }
    if (h < HH - 1) {
        float4 c = __ldg((const float4*)(hp + WW));
        s.x += c.x; s.y += c.y; s.z += c.z; s.w += c.w;
    }
    *(float4*)(out + (size_t)plane * HWs + h * WW + w0) = s;
}

extern "C" void kernel_launch(void* const* d_in, const int* in_sizes, int n_in,
                              void* d_out, int out_size) {
    const float* in = (const float*)d_in[0];
    float* out = (float*)d_out;

    cudaFuncSetAttribute(corr_mma, cudaFuncAttributeMaxDynamicSharedMemorySize, SMEM_BYTES);
    dim3 g1(HH, BB);                    // 1024 CTAs
    corr_mma<<<g1, 384, SMEM_BYTES>>>(in);

    dim3 g2(12, BB * DD);               // 4800 blocks
    box_kernel<<<g2, TPB2>>>(out);
}